// round 1
// baseline (speedup 1.0000x reference)
#include <cuda_runtime.h>
#include <math.h>

// EdgeEmbedding: pure elementwise map over edges.
// Key identity (bit-exact, see analysis): every pair has exactly 2 edges
// (one forward, one reversed), so segment-mean reconstructs pair_vec
// exactly, and SH parity cancels the reversal sign:
//   edge_length    = ||edge_vec||
//   edge_embedding = bessel(||edge_vec||) * cutoff(||edge_vec||)
//   edge_attr      = SH_l<=2(edge_vec / ||edge_vec||)
// Only input needed: edge_vec.  Output: [len (E) | emb (E,8) | attr (E,9)].

__device__ __forceinline__ void edge_math(float x, float y, float z,
                                          float& len, float* emb8, float* attr9)
{
    const float S3   = 1.7320508075688772f;   // sqrt(3)
    const float S5   = 2.2360679774997896f;   // sqrt(5)
    const float S15  = 3.8729833462074170f;   // sqrt(15)
    const float PI_F = 3.14159265358979323846f;
    const float SQRT_2_OVER_RC = 0.6324555320336759f; // sqrt(2/5)
    const float INV_RC = 0.2f;

    float r2 = fmaf(x, x, fmaf(y, y, z * z));
    float r  = sqrtf(r2);
    len = r;
    float rs  = fmaxf(r, 1e-12f);
    float inv = 1.0f / rs;

    // --- spherical harmonics l<=2 on u = vec/r ---
    float ux = x * inv, uy = y * inv, uz = z * inv;
    attr9[0] = 1.0f;
    attr9[1] = S3 * ux;
    attr9[2] = S3 * uy;
    attr9[3] = S3 * uz;
    attr9[4] = S15 * ux * uy;
    attr9[5] = S15 * uy * uz;
    attr9[6] = 0.5f * S5 * fmaf(3.0f * uz, uz, -1.0f);
    attr9[7] = S15 * ux * uz;
    attr9[8] = 0.5f * S15 * (ux * ux - uy * uy);

    // --- polynomial cutoff (p=6): 1 - 28 q^6 + 48 q^7 - 21 q^8 ---
    float q  = r * INV_RC;
    float q2 = q * q;
    float q3 = q2 * q;
    float q6 = q3 * q3;
    float env = fmaf(q6, fmaf(q, fmaf(-21.0f, q, 48.0f), -28.0f), 1.0f);
    env = (q < 1.0f) ? env : 0.0f;

    // --- bessel basis: sqrt(2/RC) * sin(k*pi*q)/r_safe * env, k=1..8 ---
    // Chebyshev recurrence: sin((k+1)t) = 2cos(t) sin(kt) - sin((k-1)t)
    float st, ct;
    sincosf(PI_F * q, &st, &ct);
    float pre  = SQRT_2_OVER_RC * inv * env;
    float twoc = 2.0f * ct;
    float sk_m1 = 0.0f, sk = st;
#pragma unroll
    for (int k = 0; k < 8; k++) {
        emb8[k] = pre * sk;
        float nxt = fmaf(twoc, sk, -sk_m1);
        sk_m1 = sk;
        sk = nxt;
    }
}

__global__ __launch_bounds__(256)
void edge_embed_vec4(const float4* __restrict__ vec4,
                     float* __restrict__ out,
                     long long E)
{
    long long nq = E >> 2;                       // quads of edges
    long long t  = (long long)blockIdx.x * blockDim.x + threadIdx.x;
    if (t >= nq) return;

    float4 v0 = vec4[3 * t + 0];
    float4 v1 = vec4[3 * t + 1];
    float4 v2 = vec4[3 * t + 2];
    float xs[4] = { v0.x, v0.w, v1.z, v2.y };
    float ys[4] = { v0.y, v1.x, v1.w, v2.z };
    float zs[4] = { v0.z, v1.y, v2.x, v2.w };

    float* out_len  = out;
    float* out_emb  = out + E;
    float* out_attr = out + 9 * E;

    float lenv[4];
    float attr[36];   // [edge][9], interleaved for float4 stores at the end

#pragma unroll
    for (int i = 0; i < 4; i++) {
        float emb[8];
        float a9[9];
        edge_math(xs[i], ys[i], zs[i], lenv[i], emb, a9);
#pragma unroll
        for (int j = 0; j < 9; j++) attr[i * 9 + j] = a9[j];
        // embedding: 8 floats per edge, 32B-aligned per edge
        float4* pe = reinterpret_cast<float4*>(out_emb + 8 * (4 * t + i));
        pe[0] = make_float4(emb[0], emb[1], emb[2], emb[3]);
        pe[1] = make_float4(emb[4], emb[5], emb[6], emb[7]);
    }

    // lengths: one float4 for 4 edges
    *reinterpret_cast<float4*>(out_len + 4 * t) =
        make_float4(lenv[0], lenv[1], lenv[2], lenv[3]);

    // attr: 36 contiguous floats (4 edges x 9), 144B per thread, 16B-aligned
    float4* pa = reinterpret_cast<float4*>(out_attr + 36 * t);
#pragma unroll
    for (int j = 0; j < 9; j++)
        pa[j] = make_float4(attr[4 * j + 0], attr[4 * j + 1],
                            attr[4 * j + 2], attr[4 * j + 3]);
}

// Scalar tail for E % 4 != 0 (not hit for E = 3M, kept for robustness).
__global__ void edge_embed_tail(const float* __restrict__ vec,
                                float* __restrict__ out,
                                long long E, long long start)
{
    long long e = start + threadIdx.x;
    if (e >= E) return;
    float x = vec[3 * e + 0], y = vec[3 * e + 1], z = vec[3 * e + 2];
    float len, emb[8], a9[9];
    edge_math(x, y, z, len, emb, a9);
    out[e] = len;
    float* oe = out + E + 8 * e;
#pragma unroll
    for (int k = 0; k < 8; k++) oe[k] = emb[k];
    float* oa = out + 9 * E + 9 * e;
#pragma unroll
    for (int j = 0; j < 9; j++) oa[j] = a9[j];
}

extern "C" void kernel_launch(void* const* d_in, const int* in_sizes, int n_in,
                              void* d_out, int out_size)
{
    const float* edge_vec = (const float*)d_in[0];
    long long E = (long long)in_sizes[0] / 3;
    float* out = (float*)d_out;

    long long nq = E >> 2;
    if (nq > 0) {
        int threads = 256;
        long long blocks = (nq + threads - 1) / threads;
        edge_embed_vec4<<<(unsigned)blocks, threads>>>(
            (const float4*)edge_vec, out, E);
    }
    long long rem = E & 3LL;
    if (rem > 0) {
        edge_embed_tail<<<1, (unsigned)rem>>>(edge_vec, out, E, E - rem);
    }
}

// round 2
// speedup vs baseline: 1.9208x; 1.9208x over previous
#include <cuda_runtime.h>
#include <math.h>
#include <stdint.h>

// EdgeEmbedding: pure elementwise map over edges (see R0 analysis: the
// segment-mean and SH-parity structure cancels bit-exactly, so
//   edge_length    = ||edge_vec||
//   edge_embedding = bessel(||edge_vec||) * cutoff(||edge_vec||)
//   edge_attr      = SH_l<=2(edge_vec / ||edge_vec||)
// Output layout: [len (E) | emb (E,8) | attr (E,9)].
//
// R1 change: one edge/thread + smem-staged transposed writeout so every
// store instruction's warp footprint is a contiguous 128B line (the R0
// 4-edge/thread layout amplified L1 store wavefronts ~8-9x).

#define EPB  256   // edges per block == threads per block
#define ROWP 257   // smem row pad (odd -> spreads banks on gather)

__device__ __forceinline__ void edge_math(float x, float y, float z,
                                          float& len, float* emb8, float* attr9)
{
    const float S3   = 1.7320508075688772f;   // sqrt(3)
    const float S5   = 2.2360679774997896f;   // sqrt(5)
    const float S15  = 3.8729833462074170f;   // sqrt(15)
    const float PI_F = 3.14159265358979323846f;
    const float SQRT_2_OVER_RC = 0.6324555320336759f; // sqrt(2/5)
    const float INV_RC = 0.2f;

    float r2 = fmaf(x, x, fmaf(y, y, z * z));
    float r  = sqrtf(r2);
    len = r;
    float rs  = fmaxf(r, 1e-12f);
    float inv = 1.0f / rs;

    // spherical harmonics l<=2 on u = vec/r
    float ux = x * inv, uy = y * inv, uz = z * inv;
    attr9[0] = 1.0f;
    attr9[1] = S3 * ux;
    attr9[2] = S3 * uy;
    attr9[3] = S3 * uz;
    attr9[4] = S15 * ux * uy;
    attr9[5] = S15 * uy * uz;
    attr9[6] = 0.5f * S5 * fmaf(3.0f * uz, uz, -1.0f);
    attr9[7] = S15 * ux * uz;
    attr9[8] = 0.5f * S15 * (ux * ux - uy * uy);

    // polynomial cutoff (p=6): 1 - 28 q^6 + 48 q^7 - 21 q^8
    float q  = r * INV_RC;
    float q2 = q * q;
    float q3 = q2 * q;
    float q6 = q3 * q3;
    float env = fmaf(q6, fmaf(q, fmaf(-21.0f, q, 48.0f), -28.0f), 1.0f);
    env = (q < 1.0f) ? env : 0.0f;

    // bessel: sqrt(2/RC) * sin(k*pi*q)/r_safe * env, k=1..8
    // Chebyshev recurrence: sin((k+1)t) = 2cos(t)sin(kt) - sin((k-1)t)
    float st, ct;
    sincosf(PI_F * q, &st, &ct);
    float pre  = SQRT_2_OVER_RC * inv * env;
    float twoc = 2.0f * ct;
    float sk_m1 = 0.0f, sk = st;
#pragma unroll
    for (int k = 0; k < 8; k++) {
        emb8[k] = pre * sk;
        float nxt = fmaf(twoc, sk, -sk_m1);
        sk_m1 = sk;
        sk = nxt;
    }
}

__global__ __launch_bounds__(EPB)
void edge_embed_smem(const float* __restrict__ vec,
                     float* __restrict__ out,
                     int E)
{
    __shared__ float emb_s[8][ROWP];
    __shared__ float attr_s[9][ROWP];

    const int tid = threadIdx.x;
    const long long base = (long long)blockIdx.x * EPB;
    const int nedge = (int)((base + EPB <= (long long)E) ? (long long)EPB
                                                         : ((long long)E - base));

    if (tid < nedge) {
        long long e = base + tid;
        float x = vec[3 * e + 0];
        float y = vec[3 * e + 1];
        float z = vec[3 * e + 2];
        float len, emb[8], a9[9];
        edge_math(x, y, z, len, emb, a9);
        out[e] = len;                         // coalesced STG.32
#pragma unroll
        for (int k = 0; k < 8; k++) emb_s[k][tid] = emb[k];
#pragma unroll
        for (int k = 0; k < 9; k++) attr_s[k][tid] = a9[k];
    }
    __syncthreads();

    // --- emb writeout: nedge*8 contiguous floats, float4 stores ---
    {
        float* oe = out + (long long)E + base * 8;
        int n4 = nedge * 2;                   // (nedge*8)/4
        if ((((uintptr_t)oe) & 15) == 0) {
            for (int m = tid; m < n4; m += EPB) {
                int s  = m << 2;
                int i  = s >> 3;
                int k0 = s & 7;
                float4 v = make_float4(emb_s[k0 + 0][i], emb_s[k0 + 1][i],
                                       emb_s[k0 + 2][i], emb_s[k0 + 3][i]);
                reinterpret_cast<float4*>(oe)[m] = v;
            }
        } else {
            int nt = nedge * 8;
            for (int s = tid; s < nt; s += EPB)
                oe[s] = emb_s[s & 7][s >> 3];
        }
    }

    // --- attr writeout: nedge*9 contiguous floats, float4 stores ---
    {
        float* oa = out + 9LL * E + base * 9;
        int ntot = nedge * 9;
        if (((ntot & 3) == 0) && ((((uintptr_t)oa) & 15) == 0)) {
            int n4 = ntot >> 2;
            for (int m = tid; m < n4; m += EPB) {
                int s = m << 2;
                float v0, v1, v2, v3;
                {
                    unsigned idx = s + 0, i = idx / 9u, k = idx - 9u * i;
                    v0 = attr_s[k][i];
                }
                {
                    unsigned idx = s + 1, i = idx / 9u, k = idx - 9u * i;
                    v1 = attr_s[k][i];
                }
                {
                    unsigned idx = s + 2, i = idx / 9u, k = idx - 9u * i;
                    v2 = attr_s[k][i];
                }
                {
                    unsigned idx = s + 3, i = idx / 9u, k = idx - 9u * i;
                    v3 = attr_s[k][i];
                }
                reinterpret_cast<float4*>(oa)[m] = make_float4(v0, v1, v2, v3);
            }
        } else {
            for (int s = tid; s < ntot; s += EPB) {
                unsigned i = (unsigned)s / 9u, k = (unsigned)s - 9u * i;
                oa[s] = attr_s[k][i];
            }
        }
    }
}

extern "C" void kernel_launch(void* const* d_in, const int* in_sizes, int n_in,
                              void* d_out, int out_size)
{
    const float* edge_vec = (const float*)d_in[0];
    int E = in_sizes[0] / 3;
    float* out = (float*)d_out;

    int blocks = (E + EPB - 1) / EPB;
    edge_embed_smem<<<blocks, EPB>>>(edge_vec, out, E);
}

// round 3
// speedup vs baseline: 2.3745x; 1.2362x over previous
#include <cuda_runtime.h>
#include <math.h>
#include <stdint.h>

// EdgeEmbedding: pure elementwise map over edges (R0 analysis: the pair
// segment-mean and SH parity cancel bit-exactly):
//   edge_length    = ||edge_vec||
//   edge_embedding = bessel(||edge_vec||) * cutoff(||edge_vec||)
//   edge_attr      = SH_l<=2(edge_vec / ||edge_vec||)
// Output layout: [len (E) | emb (E,8) | attr (E,9)].
//
// R2 changes (L1 was 84.8% = bottleneck):
//  - attr smem is LINEAR per-edge (tid*9+k): STS stride-9 is conflict-free,
//    writeout gather is a single contiguous LDS.128 per float4 (no div-by-9,
//    no 4x scalar LDS).
//  - emb skips smem: each output float4 is one thread's registers; direct
//    STG.128 (32B lane stride) is cheaper than the STS+LDS+STG round trip.

#define EPB 256   // edges per block == threads per block

__device__ __forceinline__ void edge_math(float x, float y, float z,
                                          float& len, float* emb8, float* attr9)
{
    const float S3   = 1.7320508075688772f;   // sqrt(3)
    const float S5   = 2.2360679774997896f;   // sqrt(5)
    const float S15  = 3.8729833462074170f;   // sqrt(15)
    const float PI_F = 3.14159265358979323846f;
    const float SQRT_2_OVER_RC = 0.6324555320336759f; // sqrt(2/5)
    const float INV_RC = 0.2f;

    float r2 = fmaf(x, x, fmaf(y, y, z * z));
    float r  = sqrtf(r2);
    len = r;
    float rs  = fmaxf(r, 1e-12f);
    float inv = 1.0f / rs;

    // spherical harmonics l<=2 on u = vec/r
    float ux = x * inv, uy = y * inv, uz = z * inv;
    attr9[0] = 1.0f;
    attr9[1] = S3 * ux;
    attr9[2] = S3 * uy;
    attr9[3] = S3 * uz;
    attr9[4] = S15 * ux * uy;
    attr9[5] = S15 * uy * uz;
    attr9[6] = 0.5f * S5 * fmaf(3.0f * uz, uz, -1.0f);
    attr9[7] = S15 * ux * uz;
    attr9[8] = 0.5f * S15 * (ux * ux - uy * uy);

    // polynomial cutoff (p=6): 1 - 28 q^6 + 48 q^7 - 21 q^8
    float q  = r * INV_RC;
    float q2 = q * q;
    float q3 = q2 * q;
    float q6 = q3 * q3;
    float env = fmaf(q6, fmaf(q, fmaf(-21.0f, q, 48.0f), -28.0f), 1.0f);
    env = (q < 1.0f) ? env : 0.0f;

    // bessel: sqrt(2/RC) * sin(k*pi*q)/r_safe * env, k=1..8
    // Chebyshev recurrence: sin((k+1)t) = 2cos(t)sin(kt) - sin((k-1)t)
    float st, ct;
    sincosf(PI_F * q, &st, &ct);
    float pre  = SQRT_2_OVER_RC * inv * env;
    float twoc = 2.0f * ct;
    float sk_m1 = 0.0f, sk = st;
#pragma unroll
    for (int k = 0; k < 8; k++) {
        emb8[k] = pre * sk;
        float nxt = fmaf(twoc, sk, -sk_m1);
        sk_m1 = sk;
        sk = nxt;
    }
}

__global__ __launch_bounds__(EPB)
void edge_embed_r2(const float* __restrict__ vec,
                   float* __restrict__ out,
                   int E, int emb_vec_ok)
{
    // linear attr staging: edge i's 9 floats at words [i*9, i*9+9)
    __shared__ float attr_s[EPB * 9];

    const int tid = threadIdx.x;
    const long long base = (long long)blockIdx.x * EPB;
    const int nedge = (int)(((base + EPB) <= (long long)E) ? (long long)EPB
                                                           : ((long long)E - base));

    if (tid < nedge) {
        long long e = base + tid;
        float x = vec[3 * e + 0];
        float y = vec[3 * e + 1];
        float z = vec[3 * e + 2];
        float len, emb[8], a9[9];
        edge_math(x, y, z, len, emb, a9);

        // len: naturally coalesced
        out[e] = len;

        // emb: direct from registers (each float4 belongs to one thread)
        float* oe = out + (long long)E + e * 8;
        if (emb_vec_ok) {
            float4* pe = reinterpret_cast<float4*>(oe);
            pe[0] = make_float4(emb[0], emb[1], emb[2], emb[3]);
            pe[1] = make_float4(emb[4], emb[5], emb[6], emb[7]);
        } else {
#pragma unroll
            for (int k = 0; k < 8; k++) oe[k] = emb[k];
        }

        // attr: stage linearly (stride-9 STS is bank-conflict-free)
#pragma unroll
        for (int k = 0; k < 9; k++) attr_s[tid * 9 + k] = a9[k];
    }
    __syncthreads();

    // attr writeout: nedge*9 contiguous floats
    float* oa = out + 9LL * E + base * 9;
    const int ntot = nedge * 9;
    if (nedge == EPB && emb_vec_ok) {
        // full block & 16B-aligned global base: pure LDS.128 -> STG.128
        const int n4 = (EPB * 9) / 4;   // 576
        const float4* s4 = reinterpret_cast<const float4*>(attr_s);
        float4* g4 = reinterpret_cast<float4*>(oa);
#pragma unroll
        for (int m = tid; m < n4; m += EPB)
            g4[m] = s4[m];
    } else {
        for (int s = tid; s < ntot; s += EPB)
            oa[s] = attr_s[s];
    }
}

extern "C" void kernel_launch(void* const* d_in, const int* in_sizes, int n_in,
                              void* d_out, int out_size)
{
    const float* edge_vec = (const float*)d_in[0];
    int E = in_sizes[0] / 3;
    float* out = (float*)d_out;

    // float4 paths require: emb base (out+E, per-edge offset 8e) and attr
    // block bases (9E + 2304*bid) to be 16B aligned -> E % 4 == 0.
    int emb_vec_ok = ((E & 3) == 0) ? 1 : 0;

    int blocks = (E + EPB - 1) / EPB;
    edge_embed_r2<<<blocks, EPB>>>(edge_vec, out, E, emb_vec_ok);
}

// round 4
// speedup vs baseline: 2.4880x; 1.0478x over previous
#include <cuda_runtime.h>
#include <math.h>
#include <stdint.h>

// EdgeEmbedding: pure elementwise map over edges (R0 analysis: the pair
// segment-mean and SH parity cancel bit-exactly):
//   edge_length    = ||edge_vec||
//   edge_embedding = bessel(||edge_vec||) * cutoff(||edge_vec||)
//   edge_attr      = SH_l<=2(edge_vec / ||edge_vec||)
// Output layout: [len (E) | emb (E,8) | attr (E,9)].
//
// R3 changes (no pipe saturated; shorten the per-thread dependent chain so
// memory bursts overlap better):
//  - rsqrtf(r2) gives BOTH 1/r and r=r2*inv: removes IEEE sqrtf + fdiv.
//  - __sincosf (MUFU) replaces software sincosf range reduction.
//  - __ldcs/__stcs streaming hints: every byte touched exactly once.

#define EPB 256   // edges per block == threads per block

__device__ __forceinline__ void edge_math(float x, float y, float z,
                                          float& len, float* emb8, float* attr9)
{
    const float S3   = 1.7320508075688772f;   // sqrt(3)
    const float S5   = 2.2360679774997896f;   // sqrt(5)
    const float S15  = 3.8729833462074170f;   // sqrt(15)
    const float PI_F = 3.14159265358979323846f;
    const float SQRT_2_OVER_RC = 0.6324555320336759f; // sqrt(2/5)
    const float INV_RC = 0.2f;

    float r2  = fmaf(x, x, fmaf(y, y, z * z));
    float inv = rsqrtf(fmaxf(r2, 1e-24f));    // 1/r  (single MUFU.RSQ)
    float r   = r2 * inv;                     // r = r2 / sqrt(r2)
    len = r;

    // spherical harmonics l<=2 on u = vec/r
    float ux = x * inv, uy = y * inv, uz = z * inv;
    attr9[0] = 1.0f;
    attr9[1] = S3 * ux;
    attr9[2] = S3 * uy;
    attr9[3] = S3 * uz;
    attr9[4] = S15 * ux * uy;
    attr9[5] = S15 * uy * uz;
    attr9[6] = 0.5f * S5 * fmaf(3.0f * uz, uz, -1.0f);
    attr9[7] = S15 * ux * uz;
    attr9[8] = 0.5f * S15 * (ux * ux - uy * uy);

    // polynomial cutoff (p=6): 1 - 28 q^6 + 48 q^7 - 21 q^8
    float q  = r * INV_RC;
    float q2 = q * q;
    float q3 = q2 * q;
    float q6 = q3 * q3;
    float env = fmaf(q6, fmaf(q, fmaf(-21.0f, q, 48.0f), -28.0f), 1.0f);
    env = (q < 1.0f) ? env : 0.0f;

    // bessel: sqrt(2/RC) * sin(k*pi*q)/r_safe * env, k=1..8
    // Chebyshev recurrence: sin((k+1)t) = 2cos(t)sin(kt) - sin((k-1)t)
    float st, ct;
    __sincosf(PI_F * q, &st, &ct);            // MUFU sin/cos, |x| <= ~pi
    float pre  = SQRT_2_OVER_RC * inv * env;
    float twoc = 2.0f * ct;
    float sk_m1 = 0.0f, sk = st;
#pragma unroll
    for (int k = 0; k < 8; k++) {
        emb8[k] = pre * sk;
        float nxt = fmaf(twoc, sk, -sk_m1);
        sk_m1 = sk;
        sk = nxt;
    }
}

__global__ __launch_bounds__(EPB)
void edge_embed_r3(const float* __restrict__ vec,
                   float* __restrict__ out,
                   int E, int vec_ok)
{
    // linear attr staging: edge i's 9 floats at words [i*9, i*9+9)
    __shared__ float attr_s[EPB * 9];

    const int tid = threadIdx.x;
    const long long base = (long long)blockIdx.x * EPB;
    const int nedge = (int)(((base + EPB) <= (long long)E) ? (long long)EPB
                                                           : ((long long)E - base));

    if (tid < nedge) {
        long long e = base + tid;
        float x = __ldcs(&vec[3 * e + 0]);
        float y = __ldcs(&vec[3 * e + 1]);
        float z = __ldcs(&vec[3 * e + 2]);
        float len, emb[8], a9[9];
        edge_math(x, y, z, len, emb, a9);

        // len: naturally coalesced
        __stcs(&out[e], len);

        // emb: direct from registers (each float4 belongs to one thread)
        float* oe = out + (long long)E + e * 8;
        if (vec_ok) {
            float4* pe = reinterpret_cast<float4*>(oe);
            __stcs(&pe[0], make_float4(emb[0], emb[1], emb[2], emb[3]));
            __stcs(&pe[1], make_float4(emb[4], emb[5], emb[6], emb[7]));
        } else {
#pragma unroll
            for (int k = 0; k < 8; k++) oe[k] = emb[k];
        }

        // attr: stage linearly (stride-9 STS is bank-conflict-free)
#pragma unroll
        for (int k = 0; k < 9; k++) attr_s[tid * 9 + k] = a9[k];
    }
    __syncthreads();

    // attr writeout: nedge*9 contiguous floats
    float* oa = out + 9LL * E + base * 9;
    if (nedge == EPB && vec_ok) {
        // full block & 16B-aligned base: contiguous LDS.128 -> STG.128
        const float4* s4 = reinterpret_cast<const float4*>(attr_s);
        float4* g4 = reinterpret_cast<float4*>(oa);
        __stcs(&g4[tid],           s4[tid]);
        __stcs(&g4[tid + EPB],     s4[tid + EPB]);
        if (tid < (EPB * 9) / 4 - 2 * EPB)               // 64 remaining
            __stcs(&g4[tid + 2 * EPB], s4[tid + 2 * EPB]);
    } else {
        const int ntot = nedge * 9;
        for (int s = tid; s < ntot; s += EPB)
            oa[s] = attr_s[s];
    }
}

extern "C" void kernel_launch(void* const* d_in, const int* in_sizes, int n_in,
                              void* d_out, int out_size)
{
    const float* edge_vec = (const float*)d_in[0];
    int E = in_sizes[0] / 3;
    float* out = (float*)d_out;

    // float4 paths require 16B alignment of out+E (offset 8e) and the attr
    // block bases (9E + 2304*bid)  ->  E % 4 == 0.
    int vec_ok = ((E & 3) == 0) ? 1 : 0;

    int blocks = (E + EPB - 1) / EPB;
    edge_embed_r3<<<blocks, EPB>>>(edge_vec, out, E, vec_ok);
}